// round 7
// baseline (speedup 1.0000x reference)
#include <cuda_runtime.h>
#include <cuda_bf16.h>
#include <math.h>
#include <stdint.h>

#define H 128
#define LYR 4
#define G 64
#define C 10
#define MAXN 50048
#define MAXE 600064
#define EPSV 1e-5f
#define NBLK 592           // 4 CTAs/SM x 148 SMs, all resident (grid-sync safe)

// Persistent device scratch (static, no allocation)
__device__ __align__(16) float g_h[MAXN * H];
__device__ __align__(16) float g_m[MAXN * H];
__device__ __align__(16) float g_pre[MAXN * H];
__device__ __align__(16) float g_a[MAXN * 2];
__device__ __align__(16) float g_stats[LYR * 2 * H];
__device__ __align__(16) float g_pool[G * H];
__device__ int g_deg[MAXN];
__device__ int g_off[MAXN];
__device__ int g_cursor[MAXN];
__device__ int g_adj[MAXE];          // src node per CSR slot
__device__ int g_btot[32];
__device__ unsigned g_sync;          // monotonic grid-sync ticket counter
// 9 matrices, each: hi half (64*136 words) + lo half (64*136 words)
#define BMAT_WORDS (2 * 64 * 136)
__device__ __align__(16) uint32_t g_Bsplit[9 * BMAT_WORDS];

static inline int cdiv(int a, int b) { return (a + b - 1) / b; }

// ---------------------------------------------------------------------------
// Split fp32 pair -> (hi bf16x2, lo bf16x2)
// ---------------------------------------------------------------------------
__device__ __forceinline__ uint32_t pack_split(float f0, float f1, uint32_t& lo) {
    __nv_bfloat16 h0 = __float2bfloat16_rn(f0);
    __nv_bfloat16 h1 = __float2bfloat16_rn(f1);
    __nv_bfloat16 l0 = __float2bfloat16_rn(f0 - __bfloat162float(h0));
    __nv_bfloat16 l1 = __float2bfloat16_rn(f1 - __bfloat162float(h1));
    lo = ((uint32_t)__bfloat16_as_ushort(l1) << 16) | (uint32_t)__bfloat16_as_ushort(l0);
    return ((uint32_t)__bfloat16_as_ushort(h1) << 16) | (uint32_t)__bfloat16_as_ushort(h0);
}

__device__ __forceinline__ void mma16816(float* d, const uint32_t* a,
                                         const uint32_t* b) {
    asm volatile(
        "mma.sync.aligned.m16n8k16.row.col.f32.bf16.bf16.f32 "
        "{%0,%1,%2,%3}, {%4,%5,%6,%7}, {%8,%9}, {%0,%1,%2,%3};\n"
        : "+f"(d[0]), "+f"(d[1]), "+f"(d[2]), "+f"(d[3])
        : "r"(a[0]), "r"(a[1]), "r"(a[2]), "r"(a[3]),
          "r"(b[0]), "r"(b[1]));
}

// ---------------------------------------------------------------------------
// Prep: split weight matrices into smem image layout (word kp*136 + n)
// ---------------------------------------------------------------------------
__global__ __launch_bounds__(256) void prep_kernel(
    const float* __restrict__ W_in, const float* __restrict__ Wm,
    const float* __restrict__ Wr)
{
    int mat = blockIdx.y;
    const float* W = (mat == 0) ? W_in
                   : (mat < 5) ? Wm + (mat - 1) * H * H
                               : Wr + (mat - 5) * H * H;
    uint32_t* out = g_Bsplit + mat * BMAT_WORDS;
    int p = blockIdx.x * 256 + threadIdx.x;
    int n = p >> 6;
    int kp = p & 63;
    int k = kp * 2;
    float f0 = W[k * H + n];
    float f1 = W[(k + 1) * H + n];
    uint32_t lo;
    uint32_t hi = pack_split(f0, f1, lo);
    out[kp * 136 + n] = hi;
    out[64 * 136 + kp * 136 + n] = lo;
}

// ---------------------------------------------------------------------------
// GEMM building blocks
// ---------------------------------------------------------------------------
#define SROW 136
#define HALF_WORDS (64 * SROW)                // 8704 words
#define PERS1_SMEM (4 * HALF_WORDS * 4)       // 139264 B (A + one B)
#define PERS2_SMEM (6 * HALF_WORDS * 4)       // 208896 B (A + two B)
#define GRID_PERS 148

__device__ __forceinline__ void gemm_copyB(uint32_t* dstB, const uint32_t* Bimg,
                                           int tid) {
    uint4* bs = (uint4*)dstB;
    const uint4* bg = (const uint4*)Bimg;
#pragma unroll
    for (int i = 0; i < 17; i++)
        bs[tid + i * 256] = bg[tid + i * 256];
}

__device__ __forceinline__ void gemm_splitA(uint32_t* Ab, const float* A,
                                            int M, int rowBase, int tid) {
    uint32_t* Ahi = Ab;
    uint32_t* Alo = Ab + HALF_WORDS;
    int row = tid & 127;
    int khalf = tid >> 7;
    bool ok = (rowBase + row) < M;
    const float4* Ar = (const float4*)(A + (size_t)(rowBase + row) * 128 + khalf * 64);
#pragma unroll
    for (int i = 0; i < 16; i++) {
        float4 v = ok ? Ar[i] : make_float4(0.f, 0.f, 0.f, 0.f);
        int kp = khalf * 32 + i * 2;
        uint32_t lo0, lo1;
        uint32_t hi0 = pack_split(v.x, v.y, lo0);
        uint32_t hi1 = pack_split(v.z, v.w, lo1);
        Ahi[kp * SROW + row] = hi0;
        Alo[kp * SROW + row] = lo0;
        Ahi[(kp + 1) * SROW + row] = hi1;
        Alo[(kp + 1) * SROW + row] = lo1;
    }
}

__device__ __forceinline__ void gemm_compute(const uint32_t* Ab,
    const uint32_t* Bb, int warp_m, int warp_n, int g, int tg, float acc[2][8][4])
{
    const uint32_t* Ahi = Ab;
    const uint32_t* Alo = Ab + HALF_WORDS;
#pragma unroll
    for (int mi = 0; mi < 2; mi++)
#pragma unroll
        for (int ni = 0; ni < 8; ni++)
#pragma unroll
            for (int q = 0; q < 4; q++) acc[mi][ni][q] = 0.f;

#pragma unroll
    for (int s = 0; s < 8; s++) {
        int q0 = s * 8 + tg;
        int q1 = s * 8 + 4 + tg;
        uint32_t ahi[2][4], alo[2][4];
#pragma unroll
        for (int mi = 0; mi < 2; mi++) {
            int r0 = warp_m + mi * 16 + g;
            ahi[mi][0] = Ahi[q0 * SROW + r0];
            ahi[mi][1] = Ahi[q0 * SROW + r0 + 8];
            ahi[mi][2] = Ahi[q1 * SROW + r0];
            ahi[mi][3] = Ahi[q1 * SROW + r0 + 8];
            alo[mi][0] = Alo[q0 * SROW + r0];
            alo[mi][1] = Alo[q0 * SROW + r0 + 8];
            alo[mi][2] = Alo[q1 * SROW + r0];
            alo[mi][3] = Alo[q1 * SROW + r0 + 8];
        }
#pragma unroll
        for (int ni = 0; ni < 8; ni++) {
            int cn = warp_n + ni * 8 + g;
            uint32_t bhi[2], blo[2];
            bhi[0] = Bb[q0 * SROW + cn];
            bhi[1] = Bb[q1 * SROW + cn];
            blo[0] = Bb[HALF_WORDS + q0 * SROW + cn];
            blo[1] = Bb[HALF_WORDS + q1 * SROW + cn];
#pragma unroll
            for (int mi = 0; mi < 2; mi++) {
                mma16816(acc[mi][ni], ahi[mi], bhi);
                mma16816(acc[mi][ni], ahi[mi], blo);
                mma16816(acc[mi][ni], alo[mi], bhi);
            }
        }
    }
}

__device__ __forceinline__ void gemm_store(float acc[2][8][4],
    const float* __restrict__ bias, float* __restrict__ Cm,
    int M, int rowBase, int warp_m, int warp_n, int g, int tg, int relu)
{
    float bv[8][2];
#pragma unroll
    for (int ni = 0; ni < 8; ni++) {
        int cb = warp_n + ni * 8 + 2 * tg;
        bv[ni][0] = bias[cb];
        bv[ni][1] = bias[cb + 1];
    }
#pragma unroll
    for (int mi = 0; mi < 2; mi++) {
#pragma unroll
        for (int rh = 0; rh < 2; rh++) {
            int row = rowBase + warp_m + mi * 16 + g + rh * 8;
            if (row < M) {
#pragma unroll
                for (int ni = 0; ni < 8; ni++) {
                    float vx = acc[mi][ni][rh * 2 + 0] + bv[ni][0];
                    float vy = acc[mi][ni][rh * 2 + 1] + bv[ni][1];
                    if (relu) { vx = fmaxf(vx, 0.f); vy = fmaxf(vy, 0.f); }
                    float2 o; o.x = vx; o.y = vy;
                    *(float2*)(Cm + (size_t)row * 128 + warp_n + ni * 8 + 2 * tg) = o;
                }
            }
        }
    }
}

// Persistent single GEMM (input layer): C = relu(A @ W + b). B copied once.
__global__ __launch_bounds__(256) void pers_gemm(
    int M, const float* __restrict__ A, const uint32_t* __restrict__ Bimg,
    const float* __restrict__ bias, float* __restrict__ Cm, int relu)
{
    extern __shared__ uint32_t sm[];
    uint32_t* Ab = sm;
    uint32_t* Bb = sm + 2 * HALF_WORDS;

    int tid = threadIdx.x;
    int warp = tid >> 5, lane = tid & 31;
    int g = lane >> 2, tg = lane & 3;
    int warp_m = (warp >> 1) * 32;
    int warp_n = (warp & 1) * 64;
    int ntiles = (M + 127) >> 7;

    gemm_copyB(Bb, Bimg, tid);

    for (int tile = blockIdx.x; tile < ntiles; tile += gridDim.x) {
        __syncthreads();
        gemm_splitA(Ab, A, M, tile * 128, tid);
        __syncthreads();
        float acc[2][8][4];
        gemm_compute(Ab, Bb, warp_m, warp_n, g, tg, acc);
        gemm_store(acc, bias, Cm, M, tile * 128, warp_m, warp_n, g, tg, relu);
    }
}

// Persistent dual GEMM: m = A@Wm + bm ; pre = A@Wr + br. Both B resident.
__global__ __launch_bounds__(256) void pers_dual_gemm(
    int M, const float* __restrict__ A,
    const uint32_t* __restrict__ Bm_img, const uint32_t* __restrict__ Br_img,
    const float* __restrict__ bm, const float* __restrict__ br,
    float* __restrict__ Cm, float* __restrict__ Cpre)
{
    extern __shared__ uint32_t sm[];
    uint32_t* Ab  = sm;
    uint32_t* Bmb = sm + 2 * HALF_WORDS;
    uint32_t* Brb = sm + 4 * HALF_WORDS;

    int tid = threadIdx.x;
    int warp = tid >> 5, lane = tid & 31;
    int g = lane >> 2, tg = lane & 3;
    int warp_m = (warp >> 1) * 32;
    int warp_n = (warp & 1) * 64;
    int ntiles = (M + 127) >> 7;

    gemm_copyB(Bmb, Bm_img, tid);
    gemm_copyB(Brb, Br_img, tid);

    for (int tile = blockIdx.x; tile < ntiles; tile += gridDim.x) {
        __syncthreads();
        gemm_splitA(Ab, A, M, tile * 128, tid);
        __syncthreads();
        {
            float acc[2][8][4];
            gemm_compute(Ab, Bmb, warp_m, warp_n, g, tg, acc);
            gemm_store(acc, bm, Cm, M, tile * 128, warp_m, warp_n, g, tg, 0);
        }
        {
            float acc[2][8][4];
            gemm_compute(Ab, Brb, warp_m, warp_n, g, tg, acc);
            gemm_store(acc, br, Cpre, M, tile * 128, warp_m, warp_n, g, tg, 0);
        }
    }
}

// ---------------------------------------------------------------------------
// Zero buffers (pool + all per-layer stats in one launch)
// ---------------------------------------------------------------------------
__global__ void zero2_kernel(float* __restrict__ p, int n4,
                             float* __restrict__ q, int m4) {
    int i = blockIdx.x * blockDim.x + threadIdx.x;
    float4 z = make_float4(0.f, 0.f, 0.f, 0.f);
    for (int j = i; j < n4; j += gridDim.x * blockDim.x) ((float4*)p)[j] = z;
    for (int j = i; j < m4; j += gridDim.x * blockDim.x) ((float4*)q)[j] = z;
}
__global__ void zeroi_kernel(int* __restrict__ p, int n) {
    int i = blockIdx.x * blockDim.x + threadIdx.x;
    if (i < n) p[i] = 0;
}

// ---------------------------------------------------------------------------
// CSR build: count, multi-block scan, fill (adjacency stores src directly)
// ---------------------------------------------------------------------------
__global__ __launch_bounds__(256) void count_kernel(int E, const int* __restrict__ dst) {
    int i = blockIdx.x * 256 + threadIdx.x;
    if (i < E) atomicAdd(&g_deg[dst[i]], 1);
}

#define SCB 4096   // elements per scan block (256 thr x 16)

__global__ __launch_bounds__(256) void scan1_kernel(int N) {
    __shared__ int wsum[8];
    int tid = threadIdx.x;
    int lane = tid & 31, w = tid >> 5;
    int base = blockIdx.x * SCB + tid * 16;
    int v[16];
    int s = 0;
#pragma unroll
    for (int i = 0; i < 16; i++) {
        int idx = base + i;
        v[i] = (idx < N) ? g_deg[idx] : 0;
        s += v[i];
    }
    int incl = s;
#pragma unroll
    for (int d = 1; d < 32; d <<= 1) {
        int t = __shfl_up_sync(0xFFFFFFFFu, incl, d);
        if (lane >= d) incl += t;
    }
    if (lane == 31) wsum[w] = incl;
    __syncthreads();
    if (tid == 0) {
        int c = 0;
#pragma unroll
        for (int i = 0; i < 8; i++) { int x = wsum[i]; wsum[i] = c; c += x; }
        g_btot[blockIdx.x] = c;
    }
    __syncthreads();
    int run = incl - s + wsum[w];
#pragma unroll
    for (int i = 0; i < 16; i++) {
        int idx = base + i;
        if (idx < N) g_off[idx] = run;
        run += v[i];
    }
}

__global__ void scan2_kernel(int nb) {
    if (threadIdx.x == 0) {
        int c = 0;
        for (int i = 0; i < nb; i++) { int x = g_btot[i]; g_btot[i] = c; c += x; }
    }
}

__global__ __launch_bounds__(256) void scan3_kernel(int N) {
    int i = blockIdx.x * 256 + threadIdx.x;
    if (i < N) {
        int o = g_off[i] + g_btot[i / SCB];
        g_off[i] = o;
        g_cursor[i] = o;
    }
}

__global__ __launch_bounds__(256) void fill_kernel(
    int E, const int* __restrict__ src, const int* __restrict__ dst)
{
    int i = blockIdx.x * 256 + threadIdx.x;
    if (i < E) {
        int slot = atomicAdd(&g_cursor[dst[i]], 1);
        g_adj[slot] = src[i];
    }
}

// ---------------------------------------------------------------------------
// adot (layer 0): a[n,0]=h[n]·Wa_src, a[n,1]=h[n]·Wa_dst. Warp per node.
// ---------------------------------------------------------------------------
__global__ __launch_bounds__(256) void adot_kernel(
    int N, const float* __restrict__ h, const float* __restrict__ Wa_l,
    float* __restrict__ a)
{
    __shared__ float ws[128], wd[128];
    int tid = threadIdx.x;
    if (tid < 128) ws[tid] = Wa_l[tid];
    else wd[tid - 128] = Wa_l[tid];
    __syncthreads();

    int gw = (blockIdx.x * blockDim.x + tid) >> 5;
    int lane = tid & 31;
    if (gw >= N) return;
    float4 v = ((const float4*)(h + (size_t)gw * 128))[lane];
    int k = lane * 4;
    float ss = v.x * ws[k] + v.y * ws[k + 1] + v.z * ws[k + 2] + v.w * ws[k + 3];
    float sd = v.x * wd[k] + v.y * wd[k + 1] + v.z * wd[k + 2] + v.w * wd[k + 3];
#pragma unroll
    for (int off = 16; off > 0; off >>= 1) {
        ss += __shfl_down_sync(0xFFFFFFFFu, ss, off);
        sd += __shfl_down_sync(0xFFFFFFFFu, sd, off);
    }
    if (lane == 0) { a[2 * gw] = ss; a[2 * gw + 1] = sd; }
}

// ---------------------------------------------------------------------------
// Fused message-passing + LN + norm + next-adot + pool. Grid-synced,
// persistent (NBLK CTAs, 4/SM). Gathered rows cached in smem — pre is read
// once and never written back.
// ---------------------------------------------------------------------------
__global__ __launch_bounds__(256, 4) void mpnorm_kernel(
    int N, int rpc, float invN,
    const float* __restrict__ pre_g, const float* __restrict__ m,
    const float* __restrict__ ba_l, float* __restrict__ a,
    float* __restrict__ stats,
    const float* __restrict__ gamma, const float* __restrict__ beta,
    const float* __restrict__ WaN,
    const int* __restrict__ batch, float* __restrict__ pool,
    float* __restrict__ h)
{
    extern __shared__ float sc[];            // [rpc][128] cache, then red buffers
    float* cache = sc;
    float* redS = sc + rpc * 128;
    float* redQ = redS + 8 * 128;
    __shared__ float ws[128], wd[128];

    int tid = threadIdx.x;
    int w = tid >> 5, lane = tid & 31;
    if (WaN) {
        if (tid < 128) ws[tid] = WaN[tid];
        else wd[tid - 128] = WaN[tid];
    }
    int rowBase = blockIdx.x * rpc;
    float bav = ba_l[0];
    float4 s1 = make_float4(0.f, 0.f, 0.f, 0.f);
    float4 s2 = make_float4(0.f, 0.f, 0.f, 0.f);
    const float4* m4 = (const float4*)m;

    // --- phase A: gather + stats, cache rows in smem ---
    for (int lr = w; lr < rpc; lr += 8) {
        int row = rowBase + lr;
        if (row >= N) break;
        float4 v = ((const float4*)pre_g)[row * 32 + lane];
        float ad = a[2 * row + 1] + bav;
        int off = g_off[row];
        int deg = g_deg[row];
        const int* ep = g_adj + off;
        int sn = (deg > 0) ? ep[0] : 0;
        for (int e = 0; e < deg; e++) {
            int sN = sn;
            if (e + 1 < deg) sn = ep[e + 1];
            float z = a[2 * sN] + ad;
            float gate = 1.f / (1.f + expf(-z));
            float4 mv = m4[(size_t)sN * 32 + lane];
            v.x += gate * mv.x; v.y += gate * mv.y;
            v.z += gate * mv.z; v.w += gate * mv.w;
        }
        ((float4*)cache)[lr * 32 + lane] = v;
        s1.x += v.x; s1.y += v.y; s1.z += v.z; s1.w += v.w;
        s2.x += v.x * v.x; s2.y += v.y * v.y;
        s2.z += v.z * v.z; s2.w += v.w * v.w;
    }
    *(float4*)&redS[w * 128 + lane * 4] = s1;
    *(float4*)&redQ[w * 128 + lane * 4] = s2;
    __syncthreads();
    if (tid < 128) {
        float aa = 0.f, bb = 0.f;
#pragma unroll
        for (int i = 0; i < 8; i++) { aa += redS[i * 128 + tid]; bb += redQ[i * 128 + tid]; }
        atomicAdd(&stats[tid], aa);
        atomicAdd(&stats[128 + tid], bb);
    }

    // --- device-wide sync (monotonic ticket) ---
    __threadfence();
    __syncthreads();
    if (tid == 0) {
        unsigned t = atomicAdd(&g_sync, 1u);
        unsigned target = (t / NBLK + 1u) * NBLK;
        while (*(volatile unsigned*)&g_sync < target) __nanosleep(64);
    }
    __syncthreads();
    __threadfence();

    // --- phase B: finalize stats locally, normalize cached rows ---
    float muv[4], rsv[4], gmv[4], btv[4];
#pragma unroll
    for (int i = 0; i < 4; i++) {
        int c = lane * 4 + i;
        float s = __ldcg(&stats[c]);
        float q = __ldcg(&stats[128 + c]);
        float mu = s * invN;
        float var = q * invN - mu * mu;
        muv[i] = mu;
        rsv[i] = rsqrtf(var + EPSV);
        gmv[i] = gamma[c];
        btv[i] = beta[c];
    }

    for (int lr = w; lr < rpc; lr += 8) {
        int row = rowBase + lr;
        if (row >= N) break;
        float4 p = ((const float4*)cache)[lr * 32 + lane];
        float4 v;
        v.x = fmaxf((p.x - muv[0]) * rsv[0] * gmv[0] + btv[0], 0.f);
        v.y = fmaxf((p.y - muv[1]) * rsv[1] * gmv[1] + btv[1], 0.f);
        v.z = fmaxf((p.z - muv[2]) * rsv[2] * gmv[2] + btv[2], 0.f);
        v.w = fmaxf((p.w - muv[3]) * rsv[3] * gmv[3] + btv[3], 0.f);
        ((float4*)h)[row * 32 + lane] = v;

        if (WaN) {
            int k = lane * 4;
            float ss = v.x * ws[k] + v.y * ws[k + 1] + v.z * ws[k + 2] + v.w * ws[k + 3];
            float sd = v.x * wd[k] + v.y * wd[k + 1] + v.z * wd[k + 2] + v.w * wd[k + 3];
#pragma unroll
            for (int off = 16; off > 0; off >>= 1) {
                ss += __shfl_down_sync(0xFFFFFFFFu, ss, off);
                sd += __shfl_down_sync(0xFFFFFFFFu, sd, off);
            }
            if (lane == 0) { a[2 * row] = ss; a[2 * row + 1] = sd; }
        }
        if (batch) {
            int b = batch[row];
            atomicAdd(((float4*)(pool + (size_t)b * 128)) + lane, v);
        }
    }
}

// ---------------------------------------------------------------------------
// MLP head
// ---------------------------------------------------------------------------
__global__ __launch_bounds__(256) void head_kernel(
    const float* __restrict__ pool,
    const float* __restrict__ W1, const float* __restrict__ b1,
    const float* __restrict__ W2, const float* __restrict__ b2,
    float* __restrict__ out)
{
    __shared__ float sh[G * 64];
    int tid = threadIdx.x;
    for (int o = tid; o < G * 64; o += 256) {
        int g = o >> 6, j = o & 63;
        float s = b1[j];
        const float* pr = pool + g * 128;
#pragma unroll 4
        for (int k = 0; k < 128; k++) s += pr[k] * W1[k * 64 + j];
        sh[o] = fmaxf(s, 0.f);
    }
    __syncthreads();
    for (int o = tid; o < G * C; o += 256) {
        int g = o / C, c = o % C;
        float s = b2[c];
        const float* hr = sh + g * 64;
#pragma unroll 4
        for (int k = 0; k < 64; k++) s += hr[k] * W2[k * C + c];
        out[o] = s * 0.5f;   // /TEMP
    }
}

// ---------------------------------------------------------------------------
// Launch
// ---------------------------------------------------------------------------
extern "C" void kernel_launch(void* const* d_in, const int* in_sizes, int n_in,
                              void* d_out, int out_size)
{
    const float* x     = (const float*)d_in[0];
    const int*   ei    = (const int*)d_in[1];
    const int*   batch = (const int*)d_in[2];
    const float* W_in  = (const float*)d_in[3];
    const float* b_in  = (const float*)d_in[4];
    const float* Wa    = (const float*)d_in[5];
    const float* ba    = (const float*)d_in[6];
    const float* Wm    = (const float*)d_in[7];
    const float* bm    = (const float*)d_in[8];
    const float* Wr    = (const float*)d_in[9];
    const float* br    = (const float*)d_in[10];
    const float* gamma = (const float*)d_in[11];
    const float* beta  = (const float*)d_in[12];
    const float* W1    = (const float*)d_in[13];
    const float* b1    = (const float*)d_in[14];
    const float* W2    = (const float*)d_in[15];
    const float* b2    = (const float*)d_in[16];

    int N = in_sizes[0] / 128;
    int E = in_sizes[1] / 2;
    const int* src = ei;
    const int* dst = ei + E;

    int rpc = cdiv(N, NBLK);                              // rows per CTA
    int mp_smem = (rpc * 128 + 2 * 8 * 128) * 4;          // cache + reductions

    cudaFuncSetAttribute(pers_gemm, cudaFuncAttributeMaxDynamicSharedMemorySize,
                         PERS1_SMEM);
    cudaFuncSetAttribute(pers_dual_gemm, cudaFuncAttributeMaxDynamicSharedMemorySize,
                         PERS2_SMEM);
    cudaFuncSetAttribute(mpnorm_kernel, cudaFuncAttributeMaxDynamicSharedMemorySize,
                         mp_smem);

    float *p_h, *p_m, *p_pre, *p_a, *p_pool, *p_stats;
    int* p_deg;
    uint32_t* p_B;
    cudaGetSymbolAddress((void**)&p_h, g_h);
    cudaGetSymbolAddress((void**)&p_m, g_m);
    cudaGetSymbolAddress((void**)&p_pre, g_pre);
    cudaGetSymbolAddress((void**)&p_a, g_a);
    cudaGetSymbolAddress((void**)&p_pool, g_pool);
    cudaGetSymbolAddress((void**)&p_stats, g_stats);
    cudaGetSymbolAddress((void**)&p_deg, g_deg);
    cudaGetSymbolAddress((void**)&p_B, g_Bsplit);

    int rowBlocks = cdiv(N, 8);
    int scanBlocks = cdiv(N, SCB);
    float invN = 1.0f / (float)N;

    // --- one-time per call: weights prep, zeros, CSR build ---
    prep_kernel<<<dim3(32, 9), 256>>>(W_in, Wm, Wr);
    zero2_kernel<<<16, 256>>>(p_pool, G * H / 4, p_stats, LYR * 2 * H / 4);
    zeroi_kernel<<<cdiv(N, 256), 256>>>(p_deg, N);
    count_kernel<<<cdiv(E, 256), 256>>>(E, dst);
    scan1_kernel<<<scanBlocks, 256>>>(N);
    scan2_kernel<<<1, 32>>>(scanBlocks);
    scan3_kernel<<<cdiv(N, 256), 256>>>(N);
    fill_kernel<<<cdiv(E, 256), 256>>>(E, src, dst);

    // h = relu(x @ W_in + b_in); a = h @ Wa[0]
    pers_gemm<<<GRID_PERS, 256, PERS1_SMEM>>>(N, x, p_B, b_in, p_h, 1);
    adot_kernel<<<rowBlocks, 256>>>(N, p_h, Wa, p_a);

    for (int l = 0; l < LYR; l++) {
        // m = h@Wm+bm ; pre = h@Wr+br (persistent, both B resident)
        pers_dual_gemm<<<GRID_PERS, 256, PERS2_SMEM>>>(
            N, p_h, p_B + (1 + l) * BMAT_WORDS, p_B + (5 + l) * BMAT_WORDS,
            bm + l * H, br + l * H, p_m, p_pre);
        // fused gather + LN + norm + next adot + (last) pool
        mpnorm_kernel<<<NBLK, 256, mp_smem>>>(
            N, rpc, invN, p_pre, p_m, ba + l, p_a,
            p_stats + l * 2 * H,
            gamma + l * H, beta + l * H,
            (l < 3) ? (Wa + (l + 1) * 2 * H) : nullptr,
            (l == 3) ? batch : nullptr, p_pool, p_h);
    }

    head_kernel<<<1, 256>>>(p_pool, W1, b1, W2, b2, (float*)d_out);
}

// round 8
// speedup vs baseline: 1.1318x; 1.1318x over previous
#include <cuda_runtime.h>
#include <cuda_bf16.h>
#include <math.h>
#include <stdint.h>

#define H 128
#define LYR 4
#define G 64
#define C 10
#define MAXN 50048
#define MAXE 600064
#define EPSV 1e-5f

// Persistent device scratch (static, no allocation)
__device__ __align__(16) float g_h[MAXN * H];
__device__ __align__(16) float g_m[MAXN * H];
__device__ __align__(16) float g_pre[MAXN * H];
__device__ __align__(16) float g_a[MAXN * 2];
__device__ __align__(16) float g_stats[LYR * 2 * H];
__device__ __align__(16) float g_pool[G * H];
__device__ int g_deg[MAXN];
__device__ int g_off[MAXN];
__device__ int g_cursor[MAXN];
__device__ int g_adj[MAXE];          // src node per CSR slot
__device__ int g_btot[32];
// 9 matrices, each: hi half (64*136 words) + lo half (64*136 words)
#define BMAT_WORDS (2 * 64 * 136)
__device__ __align__(16) uint32_t g_Bsplit[9 * BMAT_WORDS];

static inline int cdiv(int a, int b) { return (a + b - 1) / b; }

// ---------------------------------------------------------------------------
// Split fp32 pair -> (hi bf16x2, lo bf16x2)
// ---------------------------------------------------------------------------
__device__ __forceinline__ uint32_t pack_split(float f0, float f1, uint32_t& lo) {
    __nv_bfloat16 h0 = __float2bfloat16_rn(f0);
    __nv_bfloat16 h1 = __float2bfloat16_rn(f1);
    __nv_bfloat16 l0 = __float2bfloat16_rn(f0 - __bfloat162float(h0));
    __nv_bfloat16 l1 = __float2bfloat16_rn(f1 - __bfloat162float(h1));
    lo = ((uint32_t)__bfloat16_as_ushort(l1) << 16) | (uint32_t)__bfloat16_as_ushort(l0);
    return ((uint32_t)__bfloat16_as_ushort(h1) << 16) | (uint32_t)__bfloat16_as_ushort(h0);
}

__device__ __forceinline__ void mma16816(float* d, const uint32_t* a,
                                         const uint32_t* b) {
    asm volatile(
        "mma.sync.aligned.m16n8k16.row.col.f32.bf16.bf16.f32 "
        "{%0,%1,%2,%3}, {%4,%5,%6,%7}, {%8,%9}, {%0,%1,%2,%3};\n"
        : "+f"(d[0]), "+f"(d[1]), "+f"(d[2]), "+f"(d[3])
        : "r"(a[0]), "r"(a[1]), "r"(a[2]), "r"(a[3]),
          "r"(b[0]), "r"(b[1]));
}

// ---------------------------------------------------------------------------
// Prep: split weight matrices into smem image layout (word kp*136 + n)
// ---------------------------------------------------------------------------
__global__ __launch_bounds__(256) void prep_kernel(
    const float* __restrict__ W_in, const float* __restrict__ Wm,
    const float* __restrict__ Wr)
{
    int mat = blockIdx.y;
    const float* W = (mat == 0) ? W_in
                   : (mat < 5) ? Wm + (mat - 1) * H * H
                               : Wr + (mat - 5) * H * H;
    uint32_t* out = g_Bsplit + mat * BMAT_WORDS;
    int p = blockIdx.x * 256 + threadIdx.x;
    int n = p >> 6;
    int kp = p & 63;
    int k = kp * 2;
    float f0 = W[k * H + n];
    float f1 = W[(k + 1) * H + n];
    uint32_t lo;
    uint32_t hi = pack_split(f0, f1, lo);
    out[kp * 136 + n] = hi;
    out[64 * 136 + kp * 136 + n] = lo;
}

// ---------------------------------------------------------------------------
// GEMM building blocks
// ---------------------------------------------------------------------------
#define SROW 136
#define HALF_WORDS (64 * SROW)                // 8704 words
#define PERS1_SMEM (4 * HALF_WORDS * 4)       // 139264 B (A + one B)
#define PERS2_SMEM (6 * HALF_WORDS * 4)       // 208896 B (A + two B)
#define GRID_PERS 148

__device__ __forceinline__ void gemm_copyB(uint32_t* dstB, const uint32_t* Bimg,
                                           int tid) {
    uint4* bs = (uint4*)dstB;
    const uint4* bg = (const uint4*)Bimg;
#pragma unroll
    for (int i = 0; i < 17; i++)
        bs[tid + i * 256] = bg[tid + i * 256];
}

__device__ __forceinline__ void gemm_splitA(uint32_t* Ab, const float* A,
                                            int M, int rowBase, int tid) {
    uint32_t* Ahi = Ab;
    uint32_t* Alo = Ab + HALF_WORDS;
    int row = tid & 127;
    int khalf = tid >> 7;
    bool ok = (rowBase + row) < M;
    const float4* Ar = (const float4*)(A + (size_t)(rowBase + row) * 128 + khalf * 64);
#pragma unroll
    for (int i = 0; i < 16; i++) {
        float4 v = ok ? Ar[i] : make_float4(0.f, 0.f, 0.f, 0.f);
        int kp = khalf * 32 + i * 2;
        uint32_t lo0, lo1;
        uint32_t hi0 = pack_split(v.x, v.y, lo0);
        uint32_t hi1 = pack_split(v.z, v.w, lo1);
        Ahi[kp * SROW + row] = hi0;
        Alo[kp * SROW + row] = lo0;
        Ahi[(kp + 1) * SROW + row] = hi1;
        Alo[(kp + 1) * SROW + row] = lo1;
    }
}

__device__ __forceinline__ void gemm_compute(const uint32_t* Ab,
    const uint32_t* Bb, int warp_m, int warp_n, int g, int tg, float acc[2][8][4])
{
    const uint32_t* Ahi = Ab;
    const uint32_t* Alo = Ab + HALF_WORDS;
#pragma unroll
    for (int mi = 0; mi < 2; mi++)
#pragma unroll
        for (int ni = 0; ni < 8; ni++)
#pragma unroll
            for (int q = 0; q < 4; q++) acc[mi][ni][q] = 0.f;

#pragma unroll
    for (int s = 0; s < 8; s++) {
        int q0 = s * 8 + tg;
        int q1 = s * 8 + 4 + tg;
        uint32_t ahi[2][4], alo[2][4];
#pragma unroll
        for (int mi = 0; mi < 2; mi++) {
            int r0 = warp_m + mi * 16 + g;
            ahi[mi][0] = Ahi[q0 * SROW + r0];
            ahi[mi][1] = Ahi[q0 * SROW + r0 + 8];
            ahi[mi][2] = Ahi[q1 * SROW + r0];
            ahi[mi][3] = Ahi[q1 * SROW + r0 + 8];
            alo[mi][0] = Alo[q0 * SROW + r0];
            alo[mi][1] = Alo[q0 * SROW + r0 + 8];
            alo[mi][2] = Alo[q1 * SROW + r0];
            alo[mi][3] = Alo[q1 * SROW + r0 + 8];
        }
#pragma unroll
        for (int ni = 0; ni < 8; ni++) {
            int cn = warp_n + ni * 8 + g;
            uint32_t bhi[2], blo[2];
            bhi[0] = Bb[q0 * SROW + cn];
            bhi[1] = Bb[q1 * SROW + cn];
            blo[0] = Bb[HALF_WORDS + q0 * SROW + cn];
            blo[1] = Bb[HALF_WORDS + q1 * SROW + cn];
#pragma unroll
            for (int mi = 0; mi < 2; mi++) {
                mma16816(acc[mi][ni], ahi[mi], bhi);
                mma16816(acc[mi][ni], ahi[mi], blo);
                mma16816(acc[mi][ni], alo[mi], bhi);
            }
        }
    }
}

__device__ __forceinline__ void gemm_store(float acc[2][8][4],
    const float* __restrict__ bias, float* __restrict__ Cm,
    int M, int rowBase, int warp_m, int warp_n, int g, int tg, int relu)
{
    float bv[8][2];
#pragma unroll
    for (int ni = 0; ni < 8; ni++) {
        int cb = warp_n + ni * 8 + 2 * tg;
        bv[ni][0] = bias[cb];
        bv[ni][1] = bias[cb + 1];
    }
#pragma unroll
    for (int mi = 0; mi < 2; mi++) {
#pragma unroll
        for (int rh = 0; rh < 2; rh++) {
            int row = rowBase + warp_m + mi * 16 + g + rh * 8;
            if (row < M) {
#pragma unroll
                for (int ni = 0; ni < 8; ni++) {
                    float vx = acc[mi][ni][rh * 2 + 0] + bv[ni][0];
                    float vy = acc[mi][ni][rh * 2 + 1] + bv[ni][1];
                    if (relu) { vx = fmaxf(vx, 0.f); vy = fmaxf(vy, 0.f); }
                    float2 o; o.x = vx; o.y = vy;
                    *(float2*)(Cm + (size_t)row * 128 + warp_n + ni * 8 + 2 * tg) = o;
                }
            }
        }
    }
}

// Persistent single GEMM (input layer): C = relu(A @ W + b). B copied once.
__global__ __launch_bounds__(256) void pers_gemm(
    int M, const float* __restrict__ A, const uint32_t* __restrict__ Bimg,
    const float* __restrict__ bias, float* __restrict__ Cm, int relu)
{
    extern __shared__ uint32_t sm[];
    uint32_t* Ab = sm;
    uint32_t* Bb = sm + 2 * HALF_WORDS;

    int tid = threadIdx.x;
    int warp = tid >> 5, lane = tid & 31;
    int g = lane >> 2, tg = lane & 3;
    int warp_m = (warp >> 1) * 32;
    int warp_n = (warp & 1) * 64;
    int ntiles = (M + 127) >> 7;

    gemm_copyB(Bb, Bimg, tid);

    for (int tile = blockIdx.x; tile < ntiles; tile += gridDim.x) {
        __syncthreads();
        gemm_splitA(Ab, A, M, tile * 128, tid);
        __syncthreads();
        float acc[2][8][4];
        gemm_compute(Ab, Bb, warp_m, warp_n, g, tg, acc);
        gemm_store(acc, bias, Cm, M, tile * 128, warp_m, warp_n, g, tg, relu);
    }
}

// ---------------------------------------------------------------------------
// Persistent dual GEMM with fused input-normalization and adot.
// A_eff[r][c] = relu(Araw[r][c] * scale[c] + shift[c])  (affine LN or identity)
// Outputs: m = A_eff@Wm + bm ; pre = A_eff@Wr + br ; a[r] = A_eff[r]·(ws|wd).
// In-place Araw == pre output is safe (tile ownership is exclusive).
// ---------------------------------------------------------------------------
__global__ __launch_bounds__(256) void pers_dual_gemm(
    int M, float invN, const float* __restrict__ Araw, int useLN,
    const float* __restrict__ stats,
    const float* __restrict__ gamma, const float* __restrict__ beta,
    const float* __restrict__ Wa_l, float* __restrict__ a_out,
    const uint32_t* __restrict__ Bm_img, const uint32_t* __restrict__ Br_img,
    const float* __restrict__ bm, const float* __restrict__ br,
    float* __restrict__ Cm, float* __restrict__ Cpre)
{
    extern __shared__ uint32_t sm[];
    uint32_t* Ab  = sm;
    uint32_t* Bmb = sm + 2 * HALF_WORDS;
    uint32_t* Brb = sm + 4 * HALF_WORDS;
    __shared__ float s_scale[128], s_shift[128];
    __shared__ float s_ws[128], s_wd[128];
    __shared__ float s_pdS[2][128], s_pdD[2][128];

    int tid = threadIdx.x;
    int warp = tid >> 5, lane = tid & 31;
    int g = lane >> 2, tg = lane & 3;
    int warp_m = (warp >> 1) * 32;
    int warp_n = (warp & 1) * 64;
    int ntiles = (M + 127) >> 7;

    if (tid < 128) {
        float sc = 1.f, sh = 0.f;
        if (useLN) {
            float s = stats[tid], q = stats[128 + tid];
            float mu = s * invN;
            float var = q * invN - mu * mu;
            float rs = rsqrtf(var + EPSV);
            sc = rs * gamma[tid];
            sh = beta[tid] - mu * sc;
        }
        s_scale[tid] = sc;
        s_shift[tid] = sh;
        s_ws[tid] = Wa_l[tid];
        s_wd[tid] = Wa_l[128 + tid];
    }
    gemm_copyB(Bmb, Bm_img, tid);
    gemm_copyB(Brb, Br_img, tid);

    int row = tid & 127;
    int khalf = tid >> 7;

    for (int tile = blockIdx.x; tile < ntiles; tile += gridDim.x) {
        int rowBase = tile * 128;
        __syncthreads();   // B/scale ready; prior iter compute + a_out done
        // --- fused normalize + split A + adot partials ---
        {
            uint32_t* Ahi = Ab;
            uint32_t* Alo = Ab + HALF_WORDS;
            bool ok = (rowBase + row) < M;
            const float4* Ar = (const float4*)(Araw + (size_t)(rowBase + row) * 128 + khalf * 64);
            float ss = 0.f, sd = 0.f;
#pragma unroll
            for (int i = 0; i < 16; i++) {
                float4 p = ok ? Ar[i] : make_float4(0.f, 0.f, 0.f, 0.f);
                int k = khalf * 64 + i * 4;
                float4 v;
                v.x = fmaxf(p.x * s_scale[k + 0] + s_shift[k + 0], 0.f);
                v.y = fmaxf(p.y * s_scale[k + 1] + s_shift[k + 1], 0.f);
                v.z = fmaxf(p.z * s_scale[k + 2] + s_shift[k + 2], 0.f);
                v.w = fmaxf(p.w * s_scale[k + 3] + s_shift[k + 3], 0.f);
                if (!ok) { v.x = 0.f; v.y = 0.f; v.z = 0.f; v.w = 0.f; }
                ss += v.x * s_ws[k] + v.y * s_ws[k + 1] + v.z * s_ws[k + 2] + v.w * s_ws[k + 3];
                sd += v.x * s_wd[k] + v.y * s_wd[k + 1] + v.z * s_wd[k + 2] + v.w * s_wd[k + 3];
                int kp = khalf * 32 + i * 2;
                uint32_t lo0, lo1;
                uint32_t hi0 = pack_split(v.x, v.y, lo0);
                uint32_t hi1 = pack_split(v.z, v.w, lo1);
                Ahi[kp * SROW + row] = hi0;
                Alo[kp * SROW + row] = lo0;
                Ahi[(kp + 1) * SROW + row] = hi1;
                Alo[(kp + 1) * SROW + row] = lo1;
            }
            s_pdS[khalf][row] = ss;
            s_pdD[khalf][row] = sd;
        }
        __syncthreads();
        if (tid < 128 && rowBase + tid < M) {
            a_out[2 * (rowBase + tid)]     = s_pdS[0][tid] + s_pdS[1][tid];
            a_out[2 * (rowBase + tid) + 1] = s_pdD[0][tid] + s_pdD[1][tid];
        }
        {
            float acc[2][8][4];
            gemm_compute(Ab, Bmb, warp_m, warp_n, g, tg, acc);
            gemm_store(acc, bm, Cm, M, rowBase, warp_m, warp_n, g, tg, 0);
        }
        {
            float acc[2][8][4];
            gemm_compute(Ab, Brb, warp_m, warp_n, g, tg, acc);
            gemm_store(acc, br, Cpre, M, rowBase, warp_m, warp_n, g, tg, 0);
        }
    }
}

// ---------------------------------------------------------------------------
// Zero buffers (pool + all per-layer stats in one launch)
// ---------------------------------------------------------------------------
__global__ void zero2_kernel(float* __restrict__ p, int n4,
                             float* __restrict__ q, int m4) {
    int i = blockIdx.x * blockDim.x + threadIdx.x;
    float4 z = make_float4(0.f, 0.f, 0.f, 0.f);
    for (int j = i; j < n4; j += gridDim.x * blockDim.x) ((float4*)p)[j] = z;
    for (int j = i; j < m4; j += gridDim.x * blockDim.x) ((float4*)q)[j] = z;
}
__global__ void zeroi_kernel(int* __restrict__ p, int n) {
    int i = blockIdx.x * blockDim.x + threadIdx.x;
    if (i < n) p[i] = 0;
}

// ---------------------------------------------------------------------------
// CSR build: count, multi-block scan, fill (adjacency stores src directly)
// ---------------------------------------------------------------------------
__global__ __launch_bounds__(256) void count_kernel(int E, const int* __restrict__ dst) {
    int i = blockIdx.x * 256 + threadIdx.x;
    if (i < E) atomicAdd(&g_deg[dst[i]], 1);
}

#define SCB 4096   // elements per scan block (256 thr x 16)

__global__ __launch_bounds__(256) void scan1_kernel(int N) {
    __shared__ int wsum[8];
    int tid = threadIdx.x;
    int lane = tid & 31, w = tid >> 5;
    int base = blockIdx.x * SCB + tid * 16;
    int v[16];
    int s = 0;
#pragma unroll
    for (int i = 0; i < 16; i++) {
        int idx = base + i;
        v[i] = (idx < N) ? g_deg[idx] : 0;
        s += v[i];
    }
    int incl = s;
#pragma unroll
    for (int d = 1; d < 32; d <<= 1) {
        int t = __shfl_up_sync(0xFFFFFFFFu, incl, d);
        if (lane >= d) incl += t;
    }
    if (lane == 31) wsum[w] = incl;
    __syncthreads();
    if (tid == 0) {
        int c = 0;
#pragma unroll
        for (int i = 0; i < 8; i++) { int x = wsum[i]; wsum[i] = c; c += x; }
        g_btot[blockIdx.x] = c;
    }
    __syncthreads();
    int run = incl - s + wsum[w];
#pragma unroll
    for (int i = 0; i < 16; i++) {
        int idx = base + i;
        if (idx < N) g_off[idx] = run;
        run += v[i];
    }
}

__global__ void scan2_kernel(int nb) {
    if (threadIdx.x == 0) {
        int c = 0;
        for (int i = 0; i < nb; i++) { int x = g_btot[i]; g_btot[i] = c; c += x; }
    }
}

__global__ __launch_bounds__(256) void scan3_kernel(int N) {
    int i = blockIdx.x * 256 + threadIdx.x;
    if (i < N) {
        int o = g_off[i] + g_btot[i / SCB];
        g_off[i] = o;
        g_cursor[i] = o;
    }
}

__global__ __launch_bounds__(256) void fill_kernel(
    int E, const int* __restrict__ src, const int* __restrict__ dst)
{
    int i = blockIdx.x * 256 + threadIdx.x;
    if (i < E) {
        int slot = atomicAdd(&g_cursor[dst[i]], 1);
        g_adj[slot] = src[i];
    }
}

// ---------------------------------------------------------------------------
// Gather: pre[d] += sum_in sigmoid(a_src[s]+a_dst[d]+ba)*m[s]
// (CSR adjacency, warp per row, no atomics) + fused LN column stats.
// ---------------------------------------------------------------------------
__global__ __launch_bounds__(256) void gather_kernel(
    int N, const float* __restrict__ a, const float* __restrict__ ba_l,
    const float* __restrict__ m, float* __restrict__ pre,
    float* __restrict__ stats)
{
    __shared__ float redS[8][128], redQ[8][128];
    int tid = threadIdx.x;
    int w = tid >> 5, lane = tid & 31;
    float bav = ba_l[0];
    float4 s1 = make_float4(0.f, 0.f, 0.f, 0.f);
    float4 s2 = make_float4(0.f, 0.f, 0.f, 0.f);
    const float4* m4 = (const float4*)m;

    for (int row = blockIdx.x * 8 + w; row < N; row += gridDim.x * 8) {
        float4 v = ((const float4*)pre)[row * 32 + lane];
        float ad = a[2 * row + 1] + bav;
        int off = g_off[row];
        int deg = g_deg[row];
        const int* ep = g_adj + off;
        int sn = (deg > 0) ? ep[0] : 0;
        for (int e = 0; e < deg; e++) {
            int sN = sn;
            if (e + 1 < deg) sn = ep[e + 1];
            float z = a[2 * sN] + ad;
            float gate = 1.f / (1.f + expf(-z));
            float4 mv = m4[(size_t)sN * 32 + lane];
            v.x += gate * mv.x; v.y += gate * mv.y;
            v.z += gate * mv.z; v.w += gate * mv.w;
        }
        ((float4*)pre)[row * 32 + lane] = v;
        s1.x += v.x; s1.y += v.y; s1.z += v.z; s1.w += v.w;
        s2.x += v.x * v.x; s2.y += v.y * v.y;
        s2.z += v.z * v.z; s2.w += v.w * v.w;
    }
    *(float4*)&redS[w][lane * 4] = s1;
    *(float4*)&redQ[w][lane * 4] = s2;
    __syncthreads();
    if (tid < 128) {
        float aa = 0.f, bb = 0.f;
#pragma unroll
        for (int i = 0; i < 8; i++) { aa += redS[i][tid]; bb += redQ[i][tid]; }
        atomicAdd(&stats[tid], aa);
        atomicAdd(&stats[128 + tid], bb);
    }
}

// ---------------------------------------------------------------------------
// Final pool: normalize pre (layer 3) on the fly and pool. Warp per row.
// ---------------------------------------------------------------------------
__global__ __launch_bounds__(256) void pool_kernel(
    int N, float invN, const float* __restrict__ pre,
    const float* __restrict__ stats,
    const float* __restrict__ gamma, const float* __restrict__ beta,
    const int* __restrict__ batch, float* __restrict__ pool)
{
    int tid = threadIdx.x;
    int w = tid >> 5, lane = tid & 31;
    float sc[4], sh[4];
#pragma unroll
    for (int i = 0; i < 4; i++) {
        int c = lane * 4 + i;
        float s = stats[c], q = stats[128 + c];
        float mu = s * invN;
        float var = q * invN - mu * mu;
        float rs = rsqrtf(var + EPSV);
        sc[i] = rs * gamma[c];
        sh[i] = beta[c] - mu * sc[i];
    }
    for (int row = blockIdx.x * 8 + w; row < N; row += gridDim.x * 8) {
        float4 p = ((const float4*)pre)[row * 32 + lane];
        float4 v;
        v.x = fmaxf(p.x * sc[0] + sh[0], 0.f);
        v.y = fmaxf(p.y * sc[1] + sh[1], 0.f);
        v.z = fmaxf(p.z * sc[2] + sh[2], 0.f);
        v.w = fmaxf(p.w * sc[3] + sh[3], 0.f);
        int b = batch[row];
        atomicAdd(((float4*)(pool + (size_t)b * 128)) + lane, v);
    }
}

// ---------------------------------------------------------------------------
// MLP head
// ---------------------------------------------------------------------------
__global__ __launch_bounds__(256) void head_kernel(
    const float* __restrict__ pool,
    const float* __restrict__ W1, const float* __restrict__ b1,
    const float* __restrict__ W2, const float* __restrict__ b2,
    float* __restrict__ out)
{
    __shared__ float sh[G * 64];
    int tid = threadIdx.x;
    for (int o = tid; o < G * 64; o += 256) {
        int g = o >> 6, j = o & 63;
        float s = b1[j];
        const float* pr = pool + g * 128;
#pragma unroll 4
        for (int k = 0; k < 128; k++) s += pr[k] * W1[k * 64 + j];
        sh[o] = fmaxf(s, 0.f);
    }
    __syncthreads();
    for (int o = tid; o < G * C; o += 256) {
        int g = o / C, c = o % C;
        float s = b2[c];
        const float* hr = sh + g * 64;
#pragma unroll 4
        for (int k = 0; k < 64; k++) s += hr[k] * W2[k * C + c];
        out[o] = s * 0.5f;   // /TEMP
    }
}

// ---------------------------------------------------------------------------
// Launch
// ---------------------------------------------------------------------------
extern "C" void kernel_launch(void* const* d_in, const int* in_sizes, int n_in,
                              void* d_out, int out_size)
{
    const float* x     = (const float*)d_in[0];
    const int*   ei    = (const int*)d_in[1];
    const int*   batch = (const int*)d_in[2];
    const float* W_in  = (const float*)d_in[3];
    const float* b_in  = (const float*)d_in[4];
    const float* Wa    = (const float*)d_in[5];
    const float* ba    = (const float*)d_in[6];
    const float* Wm    = (const float*)d_in[7];
    const float* bm    = (const float*)d_in[8];
    const float* Wr    = (const float*)d_in[9];
    const float* br    = (const float*)d_in[10];
    const float* gamma = (const float*)d_in[11];
    const float* beta  = (const float*)d_in[12];
    const float* W1    = (const float*)d_in[13];
    const float* b1    = (const float*)d_in[14];
    const float* W2    = (const float*)d_in[15];
    const float* b2    = (const float*)d_in[16];

    int N = in_sizes[0] / 128;
    int E = in_sizes[1] / 2;
    const int* src = ei;
    const int* dst = ei + E;

    cudaFuncSetAttribute(pers_gemm, cudaFuncAttributeMaxDynamicSharedMemorySize,
                         PERS1_SMEM);
    cudaFuncSetAttribute(pers_dual_gemm, cudaFuncAttributeMaxDynamicSharedMemorySize,
                         PERS2_SMEM);

    float *p_h, *p_m, *p_pre, *p_a, *p_pool, *p_stats;
    int* p_deg;
    uint32_t* p_B;
    cudaGetSymbolAddress((void**)&p_h, g_h);
    cudaGetSymbolAddress((void**)&p_m, g_m);
    cudaGetSymbolAddress((void**)&p_pre, g_pre);
    cudaGetSymbolAddress((void**)&p_a, g_a);
    cudaGetSymbolAddress((void**)&p_pool, g_pool);
    cudaGetSymbolAddress((void**)&p_stats, g_stats);
    cudaGetSymbolAddress((void**)&p_deg, g_deg);
    cudaGetSymbolAddress((void**)&p_B, g_Bsplit);

    int rowBlocks = cdiv(N, 8);
    int scanBlocks = cdiv(N, SCB);
    float invN = 1.0f / (float)N;

    // --- one-time per call: weights prep, zeros, CSR build ---
    prep_kernel<<<dim3(32, 9), 256>>>(W_in, Wm, Wr);
    zero2_kernel<<<16, 256>>>(p_pool, G * H / 4, p_stats, LYR * 2 * H / 4);
    zeroi_kernel<<<cdiv(N, 256), 256>>>(p_deg, N);
    count_kernel<<<cdiv(E, 256), 256>>>(E, dst);
    scan1_kernel<<<scanBlocks, 256>>>(N);
    scan2_kernel<<<1, 32>>>(scanBlocks);
    scan3_kernel<<<cdiv(N, 256), 256>>>(N);
    fill_kernel<<<cdiv(E, 256), 256>>>(E, src, dst);

    // h = relu(x @ W_in + b_in)
    pers_gemm<<<GRID_PERS, 256, PERS1_SMEM>>>(N, x, p_B, b_in, p_h, 1);

    for (int l = 0; l < LYR; l++) {
        // A = (l==0) ? h (identity transform) : pre (inline LN+relu).
        // Fused: next adot a_l. Outputs m, pre (in-place safe).
        pers_dual_gemm<<<GRID_PERS, 256, PERS2_SMEM>>>(
            N, invN,
            (l == 0) ? p_h : p_pre, (l == 0) ? 0 : 1,
            p_stats + (l - 1) * 2 * H,
            gamma + (l - 1) * H, beta + (l - 1) * H,
            Wa + l * 2 * H, p_a,
            p_B + (1 + l) * BMAT_WORDS, p_B + (5 + l) * BMAT_WORDS,
            bm + l * H, br + l * H, p_m, p_pre);
        // pre += sum_in sigmoid(...)*m[src]; fused LN stats
        gather_kernel<<<2048, 256>>>(N, p_a, ba + l, p_m, p_pre,
                                     p_stats + l * 2 * H);
    }

    // pool = segment_sum(LN(pre_3))
    pool_kernel<<<rowBlocks, 256>>>(N, invN, p_pre, p_stats + 3 * 2 * H,
                                    gamma + 3 * H, beta + 3 * H, batch, p_pool);
    head_kernel<<<1, 256>>>(p_pool, W1, b1, W2, b2, (float*)d_out);
}

// round 9
// speedup vs baseline: 1.1989x; 1.0593x over previous
#include <cuda_runtime.h>
#include <cuda_bf16.h>
#include <math.h>
#include <stdint.h>

#define H 128
#define LYR 4
#define G 64
#define C 10
#define MAXN 50048
#define MAXE 600064
#define EPSV 1e-5f

// Persistent device scratch (static, no allocation).
// INVARIANT: g_deg, g_pool, g_stats are zero at entry (zero-initialized .bss;
// restored to zero by pool_kernel / head_kernel at the end of every call).
__device__ __align__(16) float g_h[MAXN * H];
__device__ __align__(16) float g_m[MAXN * H];
__device__ __align__(16) float g_pre[MAXN * H];
__device__ __align__(16) float g_a[MAXN * 2];
__device__ __align__(16) float g_stats[LYR * 2 * H];
__device__ __align__(16) float g_pool[G * H];
__device__ int g_deg[MAXN];
__device__ int g_off[MAXN];
__device__ int g_cursor[MAXN];
__device__ int g_adj[MAXE];          // src node per CSR slot
__device__ int g_btot[32];
// 9 matrices, each: hi half (64*136 words) + lo half (64*136 words)
#define BMAT_WORDS (2 * 64 * 136)
__device__ __align__(16) uint32_t g_Bsplit[9 * BMAT_WORDS];

static inline int cdiv(int a, int b) { return (a + b - 1) / b; }

// ---------------------------------------------------------------------------
// Split fp32 pair -> (hi bf16x2, lo bf16x2)
// ---------------------------------------------------------------------------
__device__ __forceinline__ uint32_t pack_split(float f0, float f1, uint32_t& lo) {
    __nv_bfloat16 h0 = __float2bfloat16_rn(f0);
    __nv_bfloat16 h1 = __float2bfloat16_rn(f1);
    __nv_bfloat16 l0 = __float2bfloat16_rn(f0 - __bfloat162float(h0));
    __nv_bfloat16 l1 = __float2bfloat16_rn(f1 - __bfloat162float(h1));
    lo = ((uint32_t)__bfloat16_as_ushort(l1) << 16) | (uint32_t)__bfloat16_as_ushort(l0);
    return ((uint32_t)__bfloat16_as_ushort(h1) << 16) | (uint32_t)__bfloat16_as_ushort(h0);
}

__device__ __forceinline__ void mma16816(float* d, const uint32_t* a,
                                         const uint32_t* b) {
    asm volatile(
        "mma.sync.aligned.m16n8k16.row.col.f32.bf16.bf16.f32 "
        "{%0,%1,%2,%3}, {%4,%5,%6,%7}, {%8,%9}, {%0,%1,%2,%3};\n"
        : "+f"(d[0]), "+f"(d[1]), "+f"(d[2]), "+f"(d[3])
        : "r"(a[0]), "r"(a[1]), "r"(a[2]), "r"(a[3]),
          "r"(b[0]), "r"(b[1]));
}

// ---------------------------------------------------------------------------
// Prep: split weight matrices into smem image layout (word kp*136 + n)
// ---------------------------------------------------------------------------
__global__ __launch_bounds__(256) void prep_kernel(
    const float* __restrict__ W_in, const float* __restrict__ Wm,
    const float* __restrict__ Wr)
{
    int mat = blockIdx.y;
    const float* W = (mat == 0) ? W_in
                   : (mat < 5) ? Wm + (mat - 1) * H * H
                               : Wr + (mat - 5) * H * H;
    uint32_t* out = g_Bsplit + mat * BMAT_WORDS;
    int p = blockIdx.x * 256 + threadIdx.x;
    int n = p >> 6;
    int kp = p & 63;
    int k = kp * 2;
    float f0 = W[k * H + n];
    float f1 = W[(k + 1) * H + n];
    uint32_t lo;
    uint32_t hi = pack_split(f0, f1, lo);
    out[kp * 136 + n] = hi;
    out[64 * 136 + kp * 136 + n] = lo;
}

// ---------------------------------------------------------------------------
// GEMM building blocks
// ---------------------------------------------------------------------------
#define SROW 136
#define HALF_WORDS (64 * SROW)                // 8704 words
#define PERS1_SMEM (4 * HALF_WORDS * 4)       // 139264 B (A + one B)
#define PERS2_SMEM (6 * HALF_WORDS * 4)       // 208896 B (A + two B)
#define GRID_PERS 148

__device__ __forceinline__ void gemm_copyB(uint32_t* dstB, const uint32_t* Bimg,
                                           int tid) {
    uint4* bs = (uint4*)dstB;
    const uint4* bg = (const uint4*)Bimg;
#pragma unroll
    for (int i = 0; i < 17; i++)
        bs[tid + i * 256] = bg[tid + i * 256];
}

__device__ __forceinline__ void gemm_splitA(uint32_t* Ab, const float* A,
                                            int M, int rowBase, int tid) {
    uint32_t* Ahi = Ab;
    uint32_t* Alo = Ab + HALF_WORDS;
    int row = tid & 127;
    int khalf = tid >> 7;
    bool ok = (rowBase + row) < M;
    const float4* Ar = (const float4*)(A + (size_t)(rowBase + row) * 128 + khalf * 64);
#pragma unroll
    for (int i = 0; i < 16; i++) {
        float4 v = ok ? Ar[i] : make_float4(0.f, 0.f, 0.f, 0.f);
        int kp = khalf * 32 + i * 2;
        uint32_t lo0, lo1;
        uint32_t hi0 = pack_split(v.x, v.y, lo0);
        uint32_t hi1 = pack_split(v.z, v.w, lo1);
        Ahi[kp * SROW + row] = hi0;
        Alo[kp * SROW + row] = lo0;
        Ahi[(kp + 1) * SROW + row] = hi1;
        Alo[(kp + 1) * SROW + row] = lo1;
    }
}

__device__ __forceinline__ void gemm_compute(const uint32_t* Ab,
    const uint32_t* Bb, int warp_m, int warp_n, int g, int tg, float acc[2][8][4])
{
    const uint32_t* Ahi = Ab;
    const uint32_t* Alo = Ab + HALF_WORDS;
#pragma unroll
    for (int mi = 0; mi < 2; mi++)
#pragma unroll
        for (int ni = 0; ni < 8; ni++)
#pragma unroll
            for (int q = 0; q < 4; q++) acc[mi][ni][q] = 0.f;

#pragma unroll
    for (int s = 0; s < 8; s++) {
        int q0 = s * 8 + tg;
        int q1 = s * 8 + 4 + tg;
        uint32_t ahi[2][4], alo[2][4];
#pragma unroll
        for (int mi = 0; mi < 2; mi++) {
            int r0 = warp_m + mi * 16 + g;
            ahi[mi][0] = Ahi[q0 * SROW + r0];
            ahi[mi][1] = Ahi[q0 * SROW + r0 + 8];
            ahi[mi][2] = Ahi[q1 * SROW + r0];
            ahi[mi][3] = Ahi[q1 * SROW + r0 + 8];
            alo[mi][0] = Alo[q0 * SROW + r0];
            alo[mi][1] = Alo[q0 * SROW + r0 + 8];
            alo[mi][2] = Alo[q1 * SROW + r0];
            alo[mi][3] = Alo[q1 * SROW + r0 + 8];
        }
#pragma unroll
        for (int ni = 0; ni < 8; ni++) {
            int cn = warp_n + ni * 8 + g;
            uint32_t bhi[2], blo[2];
            bhi[0] = Bb[q0 * SROW + cn];
            bhi[1] = Bb[q1 * SROW + cn];
            blo[0] = Bb[HALF_WORDS + q0 * SROW + cn];
            blo[1] = Bb[HALF_WORDS + q1 * SROW + cn];
#pragma unroll
            for (int mi = 0; mi < 2; mi++) {
                mma16816(acc[mi][ni], ahi[mi], bhi);
                mma16816(acc[mi][ni], ahi[mi], blo);
                mma16816(acc[mi][ni], alo[mi], bhi);
            }
        }
    }
}

__device__ __forceinline__ void gemm_store(float acc[2][8][4],
    const float* __restrict__ bias, float* __restrict__ Cm,
    int M, int rowBase, int warp_m, int warp_n, int g, int tg, int relu)
{
    float bv[8][2];
#pragma unroll
    for (int ni = 0; ni < 8; ni++) {
        int cb = warp_n + ni * 8 + 2 * tg;
        bv[ni][0] = bias[cb];
        bv[ni][1] = bias[cb + 1];
    }
#pragma unroll
    for (int mi = 0; mi < 2; mi++) {
#pragma unroll
        for (int rh = 0; rh < 2; rh++) {
            int row = rowBase + warp_m + mi * 16 + g + rh * 8;
            if (row < M) {
#pragma unroll
                for (int ni = 0; ni < 8; ni++) {
                    float vx = acc[mi][ni][rh * 2 + 0] + bv[ni][0];
                    float vy = acc[mi][ni][rh * 2 + 1] + bv[ni][1];
                    if (relu) { vx = fmaxf(vx, 0.f); vy = fmaxf(vy, 0.f); }
                    float2 o; o.x = vx; o.y = vy;
                    *(float2*)(Cm + (size_t)row * 128 + warp_n + ni * 8 + 2 * tg) = o;
                }
            }
        }
    }
}

// Persistent single GEMM (input layer): C = relu(A @ W + b). B copied once.
__global__ __launch_bounds__(256) void pers_gemm(
    int M, const float* __restrict__ A, const uint32_t* __restrict__ Bimg,
    const float* __restrict__ bias, float* __restrict__ Cm, int relu)
{
    extern __shared__ uint32_t sm[];
    uint32_t* Ab = sm;
    uint32_t* Bb = sm + 2 * HALF_WORDS;

    int tid = threadIdx.x;
    int warp = tid >> 5, lane = tid & 31;
    int g = lane >> 2, tg = lane & 3;
    int warp_m = (warp >> 1) * 32;
    int warp_n = (warp & 1) * 64;
    int ntiles = (M + 127) >> 7;

    gemm_copyB(Bb, Bimg, tid);

    for (int tile = blockIdx.x; tile < ntiles; tile += gridDim.x) {
        __syncthreads();
        gemm_splitA(Ab, A, M, tile * 128, tid);
        __syncthreads();
        float acc[2][8][4];
        gemm_compute(Ab, Bb, warp_m, warp_n, g, tg, acc);
        gemm_store(acc, bias, Cm, M, tile * 128, warp_m, warp_n, g, tg, relu);
    }
}

// ---------------------------------------------------------------------------
// Persistent dual GEMM with fused input-normalization and adot.
// A_eff[r][c] = relu(Araw[r][c] * scale[c] + shift[c])  (affine LN or identity)
// Outputs: m = A_eff@Wm + bm ; pre = A_eff@Wr + br ; a[r] = A_eff[r]·(ws|wd).
// In-place Araw == pre output is safe (tile ownership is exclusive).
// ---------------------------------------------------------------------------
__global__ __launch_bounds__(256) void pers_dual_gemm(
    int M, float invN, const float* __restrict__ Araw, int useLN,
    const float* __restrict__ stats,
    const float* __restrict__ gamma, const float* __restrict__ beta,
    const float* __restrict__ Wa_l, float* __restrict__ a_out,
    const uint32_t* __restrict__ Bm_img, const uint32_t* __restrict__ Br_img,
    const float* __restrict__ bm, const float* __restrict__ br,
    float* __restrict__ Cm, float* __restrict__ Cpre)
{
    extern __shared__ uint32_t sm[];
    uint32_t* Ab  = sm;
    uint32_t* Bmb = sm + 2 * HALF_WORDS;
    uint32_t* Brb = sm + 4 * HALF_WORDS;
    __shared__ float s_scale[128], s_shift[128];
    __shared__ float s_ws[128], s_wd[128];
    __shared__ float s_pdS[2][128], s_pdD[2][128];

    int tid = threadIdx.x;
    int warp = tid >> 5, lane = tid & 31;
    int g = lane >> 2, tg = lane & 3;
    int warp_m = (warp >> 1) * 32;
    int warp_n = (warp & 1) * 64;
    int ntiles = (M + 127) >> 7;

    if (tid < 128) {
        float sc = 1.f, sh = 0.f;
        if (useLN) {
            float s = stats[tid], q = stats[128 + tid];
            float mu = s * invN;
            float var = q * invN - mu * mu;
            float rs = rsqrtf(var + EPSV);
            sc = rs * gamma[tid];
            sh = beta[tid] - mu * sc;
        }
        s_scale[tid] = sc;
        s_shift[tid] = sh;
        s_ws[tid] = Wa_l[tid];
        s_wd[tid] = Wa_l[128 + tid];
    }
    gemm_copyB(Bmb, Bm_img, tid);
    gemm_copyB(Brb, Br_img, tid);

    int row = tid & 127;
    int khalf = tid >> 7;

    for (int tile = blockIdx.x; tile < ntiles; tile += gridDim.x) {
        int rowBase = tile * 128;
        __syncthreads();   // B/scale ready; prior iter compute + a_out done
        // --- fused normalize + split A + adot partials ---
        {
            uint32_t* Ahi = Ab;
            uint32_t* Alo = Ab + HALF_WORDS;
            bool ok = (rowBase + row) < M;
            const float4* Ar = (const float4*)(Araw + (size_t)(rowBase + row) * 128 + khalf * 64);
            float ss = 0.f, sd = 0.f;
#pragma unroll
            for (int i = 0; i < 16; i++) {
                float4 p = ok ? Ar[i] : make_float4(0.f, 0.f, 0.f, 0.f);
                int k = khalf * 64 + i * 4;
                float4 v;
                v.x = fmaxf(p.x * s_scale[k + 0] + s_shift[k + 0], 0.f);
                v.y = fmaxf(p.y * s_scale[k + 1] + s_shift[k + 1], 0.f);
                v.z = fmaxf(p.z * s_scale[k + 2] + s_shift[k + 2], 0.f);
                v.w = fmaxf(p.w * s_scale[k + 3] + s_shift[k + 3], 0.f);
                if (!ok) { v.x = 0.f; v.y = 0.f; v.z = 0.f; v.w = 0.f; }
                ss += v.x * s_ws[k] + v.y * s_ws[k + 1] + v.z * s_ws[k + 2] + v.w * s_ws[k + 3];
                sd += v.x * s_wd[k] + v.y * s_wd[k + 1] + v.z * s_wd[k + 2] + v.w * s_wd[k + 3];
                int kp = khalf * 32 + i * 2;
                uint32_t lo0, lo1;
                uint32_t hi0 = pack_split(v.x, v.y, lo0);
                uint32_t hi1 = pack_split(v.z, v.w, lo1);
                Ahi[kp * SROW + row] = hi0;
                Alo[kp * SROW + row] = lo0;
                Ahi[(kp + 1) * SROW + row] = hi1;
                Alo[(kp + 1) * SROW + row] = lo1;
            }
            s_pdS[khalf][row] = ss;
            s_pdD[khalf][row] = sd;
        }
        __syncthreads();
        if (tid < 128 && rowBase + tid < M) {
            a_out[2 * (rowBase + tid)]     = s_pdS[0][tid] + s_pdS[1][tid];
            a_out[2 * (rowBase + tid) + 1] = s_pdD[0][tid] + s_pdD[1][tid];
        }
        {
            float acc[2][8][4];
            gemm_compute(Ab, Bmb, warp_m, warp_n, g, tg, acc);
            gemm_store(acc, bm, Cm, M, rowBase, warp_m, warp_n, g, tg, 0);
        }
        {
            float acc[2][8][4];
            gemm_compute(Ab, Brb, warp_m, warp_n, g, tg, acc);
            gemm_store(acc, br, Cpre, M, rowBase, warp_m, warp_n, g, tg, 0);
        }
    }
}

// ---------------------------------------------------------------------------
// CSR build: count (g_deg is zero at entry by invariant), scan, fill
// ---------------------------------------------------------------------------
__global__ __launch_bounds__(256) void count_kernel(int E, const int* __restrict__ dst) {
    int i = blockIdx.x * 256 + threadIdx.x;
    if (i < E) atomicAdd(&g_deg[dst[i]], 1);
}

#define SCB 4096   // elements per scan block (256 thr x 16)

__global__ __launch_bounds__(256) void scan1_kernel(int N) {
    __shared__ int wsum[8];
    int tid = threadIdx.x;
    int lane = tid & 31, w = tid >> 5;
    int base = blockIdx.x * SCB + tid * 16;
    int v[16];
    int s = 0;
#pragma unroll
    for (int i = 0; i < 16; i++) {
        int idx = base + i;
        v[i] = (idx < N) ? g_deg[idx] : 0;
        s += v[i];
    }
    int incl = s;
#pragma unroll
    for (int d = 1; d < 32; d <<= 1) {
        int t = __shfl_up_sync(0xFFFFFFFFu, incl, d);
        if (lane >= d) incl += t;
    }
    if (lane == 31) wsum[w] = incl;
    __syncthreads();
    if (tid == 0) {
        int c = 0;
#pragma unroll
        for (int i = 0; i < 8; i++) { int x = wsum[i]; wsum[i] = c; c += x; }
        g_btot[blockIdx.x] = c;
    }
    __syncthreads();
    int run = incl - s + wsum[w];
#pragma unroll
    for (int i = 0; i < 16; i++) {
        int idx = base + i;
        if (idx < N) g_off[idx] = run;
        run += v[i];
    }
}

// scan3: adds inline prefix of block totals (nb <= 13) — replaces scan2+scan3
__global__ __launch_bounds__(256) void scan3_kernel(int N) {
    int i = blockIdx.x * 256 + threadIdx.x;
    if (i < N) {
        int b = i / SCB;
        int add = 0;
        for (int j = 0; j < b; j++) add += g_btot[j];
        int o = g_off[i] + add;
        g_off[i] = o;
        g_cursor[i] = o;
    }
}

__global__ __launch_bounds__(256) void fill_kernel(
    int E, const int* __restrict__ src, const int* __restrict__ dst)
{
    int i = blockIdx.x * 256 + threadIdx.x;
    if (i < E) {
        int slot = atomicAdd(&g_cursor[dst[i]], 1);
        g_adj[slot] = src[i];
    }
}

// ---------------------------------------------------------------------------
// Gather: pre[d] += sum_in sigmoid(a_src[s]+a_dst[d]+ba)*m[s]
// CSR, warp per row, 1-deep prefetch of (m row, a_src). Fused LN stats.
// ---------------------------------------------------------------------------
__global__ __launch_bounds__(256) void gather_kernel(
    int N, const float* __restrict__ a, const float* __restrict__ ba_l,
    const float* __restrict__ m, float* __restrict__ pre,
    float* __restrict__ stats)
{
    __shared__ float redS[8][128], redQ[8][128];
    int tid = threadIdx.x;
    int w = tid >> 5, lane = tid & 31;
    float bav = ba_l[0];
    float4 s1 = make_float4(0.f, 0.f, 0.f, 0.f);
    float4 s2 = make_float4(0.f, 0.f, 0.f, 0.f);
    const float4* m4 = (const float4*)m;

    for (int row = blockIdx.x * 8 + w; row < N; row += gridDim.x * 8) {
        float4 v = ((const float4*)pre)[row * 32 + lane];
        float ad = a[2 * row + 1] + bav;
        int off = g_off[row];
        int deg = g_deg[row];
        const int* ep = g_adj + off;
        if (deg > 0) {
            int s0 = ep[0];
            float4 mv_n = m4[(size_t)s0 * 32 + lane];
            float z_n = a[2 * s0];
            for (int e = 0; e < deg; e++) {
                float4 mv = mv_n;
                float z = z_n + ad;
                if (e + 1 < deg) {
                    int sn = ep[e + 1];
                    mv_n = m4[(size_t)sn * 32 + lane];
                    z_n = a[2 * sn];
                }
                float gate = 1.f / (1.f + __expf(-z));
                v.x += gate * mv.x; v.y += gate * mv.y;
                v.z += gate * mv.z; v.w += gate * mv.w;
            }
        }
        ((float4*)pre)[row * 32 + lane] = v;
        s1.x += v.x; s1.y += v.y; s1.z += v.z; s1.w += v.w;
        s2.x += v.x * v.x; s2.y += v.y * v.y;
        s2.z += v.z * v.z; s2.w += v.w * v.w;
    }
    *(float4*)&redS[w][lane * 4] = s1;
    *(float4*)&redQ[w][lane * 4] = s2;
    __syncthreads();
    if (tid < 128) {
        float aa = 0.f, bb = 0.f;
#pragma unroll
        for (int i = 0; i < 8; i++) { aa += redS[i][tid]; bb += redQ[i][tid]; }
        atomicAdd(&stats[tid], aa);
        atomicAdd(&stats[128 + tid], bb);
    }
}

// ---------------------------------------------------------------------------
// Final pool: normalize pre (layer 3) on the fly and pool. Warp per row.
// Also restores g_deg = 0 (state invariant for the next call).
// ---------------------------------------------------------------------------
__global__ __launch_bounds__(256) void pool_kernel(
    int N, float invN, const float* __restrict__ pre,
    const float* __restrict__ stats,
    const float* __restrict__ gamma, const float* __restrict__ beta,
    const int* __restrict__ batch, float* __restrict__ pool)
{
    int tid = threadIdx.x;
    int w = tid >> 5, lane = tid & 31;
    float sc[4], sh[4];
#pragma unroll
    for (int i = 0; i < 4; i++) {
        int c = lane * 4 + i;
        float s = stats[c], q = stats[128 + c];
        float mu = s * invN;
        float var = q * invN - mu * mu;
        float rs = rsqrtf(var + EPSV);
        sc[i] = rs * gamma[c];
        sh[i] = beta[c] - mu * sc[i];
    }
    for (int row = blockIdx.x * 8 + w; row < N; row += gridDim.x * 8) {
        float4 p = ((const float4*)pre)[row * 32 + lane];
        float4 v;
        v.x = fmaxf(p.x * sc[0] + sh[0], 0.f);
        v.y = fmaxf(p.y * sc[1] + sh[1], 0.f);
        v.z = fmaxf(p.z * sc[2] + sh[2], 0.f);
        v.w = fmaxf(p.w * sc[3] + sh[3], 0.f);
        int b = batch[row];
        atomicAdd(((float4*)(pool + (size_t)b * 128)) + lane, v);
        if (lane == 0) g_deg[row] = 0;     // restore invariant
    }
}

// ---------------------------------------------------------------------------
// MLP head; restores g_pool and g_stats to zero (state invariant).
// ---------------------------------------------------------------------------
__global__ __launch_bounds__(256) void head_kernel(
    float* __restrict__ pool,
    const float* __restrict__ W1, const float* __restrict__ b1,
    const float* __restrict__ W2, const float* __restrict__ b2,
    float* __restrict__ out, float* __restrict__ stats)
{
    __shared__ float sh[G * 64];
    int tid = threadIdx.x;
    for (int o = tid; o < G * 64; o += 256) {
        int g = o >> 6, j = o & 63;
        float s = b1[j];
        const float* pr = pool + g * 128;
#pragma unroll 4
        for (int k = 0; k < 128; k++) s += pr[k] * W1[k * 64 + j];
        sh[o] = fmaxf(s, 0.f);
    }
    __syncthreads();            // all reads of pool complete
    for (int o = tid; o < G * H; o += 256) pool[o] = 0.f;
    for (int o = tid; o < LYR * 2 * H; o += 256) stats[o] = 0.f;
    for (int o = tid; o < G * C; o += 256) {
        int g = o / C, c = o % C;
        float s = b2[c];
        const float* hr = sh + g * 64;
#pragma unroll 4
        for (int k = 0; k < 64; k++) s += hr[k] * W2[k * C + c];
        out[o] = s * 0.5f;   // /TEMP
    }
}

// ---------------------------------------------------------------------------
// Launch
// ---------------------------------------------------------------------------
extern "C" void kernel_launch(void* const* d_in, const int* in_sizes, int n_in,
                              void* d_out, int out_size)
{
    const float* x     = (const float*)d_in[0];
    const int*   ei    = (const int*)d_in[1];
    const int*   batch = (const int*)d_in[2];
    const float* W_in  = (const float*)d_in[3];
    const float* b_in  = (const float*)d_in[4];
    const float* Wa    = (const float*)d_in[5];
    const float* ba    = (const float*)d_in[6];
    const float* Wm    = (const float*)d_in[7];
    const float* bm    = (const float*)d_in[8];
    const float* Wr    = (const float*)d_in[9];
    const float* br    = (const float*)d_in[10];
    const float* gamma = (const float*)d_in[11];
    const float* beta  = (const float*)d_in[12];
    const float* W1    = (const float*)d_in[13];
    const float* b1    = (const float*)d_in[14];
    const float* W2    = (const float*)d_in[15];
    const float* b2    = (const float*)d_in[16];

    int N = in_sizes[0] / 128;
    int E = in_sizes[1] / 2;
    const int* src = ei;
    const int* dst = ei + E;

    cudaFuncSetAttribute(pers_gemm, cudaFuncAttributeMaxDynamicSharedMemorySize,
                         PERS1_SMEM);
    cudaFuncSetAttribute(pers_dual_gemm, cudaFuncAttributeMaxDynamicSharedMemorySize,
                         PERS2_SMEM);

    float *p_h, *p_m, *p_pre, *p_a, *p_pool, *p_stats;
    uint32_t* p_B;
    cudaGetSymbolAddress((void**)&p_h, g_h);
    cudaGetSymbolAddress((void**)&p_m, g_m);
    cudaGetSymbolAddress((void**)&p_pre, g_pre);
    cudaGetSymbolAddress((void**)&p_a, g_a);
    cudaGetSymbolAddress((void**)&p_pool, g_pool);
    cudaGetSymbolAddress((void**)&p_stats, g_stats);
    cudaGetSymbolAddress((void**)&p_B, g_Bsplit);

    int rowBlocks = cdiv(N, 8);
    int scanBlocks = cdiv(N, SCB);
    float invN = 1.0f / (float)N;

    // --- one-time per call: weights prep + CSR build (g_deg zero by invariant)
    prep_kernel<<<dim3(32, 9), 256>>>(W_in, Wm, Wr);
    count_kernel<<<cdiv(E, 256), 256>>>(E, dst);
    scan1_kernel<<<scanBlocks, 256>>>(N);
    scan3_kernel<<<cdiv(N, 256), 256>>>(N);
    fill_kernel<<<cdiv(E, 256), 256>>>(E, src, dst);

    // h = relu(x @ W_in + b_in)
    pers_gemm<<<GRID_PERS, 256, PERS1_SMEM>>>(N, x, p_B, b_in, p_h, 1);

    for (int l = 0; l < LYR; l++) {
        // A = (l==0) ? h (identity) : pre (inline LN+relu). Fused next adot.
        pers_dual_gemm<<<GRID_PERS, 256, PERS2_SMEM>>>(
            N, invN,
            (l == 0) ? p_h : p_pre, (l == 0) ? 0 : 1,
            p_stats + (l - 1) * 2 * H,
            gamma + (l - 1) * H, beta + (l - 1) * H,
            Wa + l * 2 * H, p_a,
            p_B + (1 + l) * BMAT_WORDS, p_B + (5 + l) * BMAT_WORDS,
            bm + l * H, br + l * H, p_m, p_pre);
        // pre += sum_in sigmoid(...)*m[src]; fused LN stats
        gather_kernel<<<2048, 256>>>(N, p_a, ba + l, p_m, p_pre,
                                     p_stats + l * 2 * H);
    }

    // pool = segment_sum(LN(pre_3)); restores g_deg
    pool_kernel<<<rowBlocks, 256>>>(N, invN, p_pre, p_stats + 3 * 2 * H,
                                    gamma + 3 * H, beta + 3 * H, batch, p_pool);
    // head; restores g_pool/g_stats
    head_kernel<<<1, 256>>>(p_pool, W1, b1, W2, b2, (float*)d_out, p_stats);
}